// round 1
// baseline (speedup 1.0000x reference)
#include <cuda_runtime.h>
#include <math.h>

// Problem constants
#define B_   16
#define Q_   900
#define C_   512
#define T_   40
#define L_   91
#define BQ_  (B_ * Q_)     // 14400
#define BT_  (B_ * T_)     // 640

// GEMM tiling
#define BM 64
#define BN 128
#define BK 16
#define APAD 20      // As row stride (floats): keeps float4 alignment, breaks conflicts
#define BPAD 132     // Bs row stride (floats)

// Scratch (device globals: allocation-free)
__device__ float g_feat[BQ_ * C_];    // focal pos-neg feature, [BQ, C]
__device__ float g_lm[BT_ * C_];      // normalized label map rows, [BT, C]
__device__ float g_tbox[BT_ * 8];     // per target: cx,cy,w,h, x0,y0,x1,y1

// ---------------- f32x2 helpers ----------------
__device__ __forceinline__ unsigned long long pack2(float x, float y) {
    unsigned long long r;
    asm("mov.b64 %0, {%1, %2};" : "=l"(r) : "f"(x), "f"(y));
    return r;
}
__device__ __forceinline__ void fma2(unsigned long long& d,
                                     unsigned long long a,
                                     unsigned long long b) {
    asm("fma.rn.f32x2 %0, %1, %2, %0;" : "+l"(d) : "l"(a), "l"(b));
}
__device__ __forceinline__ float2 unpack2(unsigned long long v) {
    float2 r;
    asm("mov.b64 {%0, %1}, %2;" : "=f"(r.x), "=f"(r.y) : "l"(v));
    return r;
}

// ---------------- kernel 1: target prep ----------------
// One block per target row j in [0, BT): gather label map row, normalize,
// stash target box (center + corners).
__global__ void prep_targets_kernel(const float* __restrict__ label_maps,
                                    const float* __restrict__ boxes,
                                    const int*   __restrict__ class_labels) {
    int j = blockIdx.x;                 // 0..639
    int b = j / T_;
    int cls = class_labels[j];
    const float* row = label_maps + ((size_t)b * L_ + cls) * C_;

    float s = 0.f;
    for (int c = threadIdx.x; c < C_; c += 128) s += row[c];
    #pragma unroll
    for (int o = 16; o; o >>= 1) s += __shfl_xor_sync(0xffffffffu, s, o);
    __shared__ float red[4];
    if ((threadIdx.x & 31) == 0) red[threadIdx.x >> 5] = s;
    __syncthreads();
    float tot = red[0] + red[1] + red[2] + red[3];

    for (int c = threadIdx.x; c < C_; c += 128)
        g_lm[(size_t)j * C_ + c] = row[c] / tot;

    if (threadIdx.x == 0) {
        float cx = boxes[j * 4 + 0], cy = boxes[j * 4 + 1];
        float w  = boxes[j * 4 + 2], h  = boxes[j * 4 + 3];
        float* o = g_tbox + j * 8;
        o[0] = cx; o[1] = cy; o[2] = w; o[3] = h;
        o[4] = cx - 0.5f * w; o[5] = cy - 0.5f * h;
        o[6] = cx + 0.5f * w; o[7] = cy + 0.5f * h;
    }
}

// ---------------- kernel 2: focal features ----------------
__device__ __forceinline__ float focal_feat(float x) {
    float p = 1.f / (1.f + expf(-x));
    float q = 1.f - p;
    float neg = 0.75f * p * p * (-logf(q + 1e-8f));   // (1-ALPHA)=0.75, GAMMA=2
    float pos = 0.25f * q * q * (-logf(p + 1e-8f));   // ALPHA=0.25
    return pos - neg;
}

__global__ void prep_feat_kernel(const float* __restrict__ logits) {
    int i = (blockIdx.x * blockDim.x + threadIdx.x) * 4;
    float4 x = *(const float4*)(logits + i);
    float4 r;
    r.x = focal_feat(x.x);
    r.y = focal_feat(x.y);
    r.z = focal_feat(x.z);
    r.w = focal_feat(x.w);
    *(float4*)(g_feat + i) = r;
}

// ---------------- kernel 3: GEMM + fused box-cost epilogue ----------------
// cost[m, n] = 5 * L1(center boxes) + 2 * (feat[m,:] . lm[n,:]) + 2 * (-GIoU)
__global__ __launch_bounds__(256) void cost_kernel(
    const float* __restrict__ pred_boxes,
    float* __restrict__ out) {

    __shared__ float As[BM][APAD];   // [m][k] — a-reads are warp broadcasts
    __shared__ float Bs[BK][BPAD];   // [k][n] — b-reads are vector LDS.128

    const int tid = threadIdx.x;
    const int tx = tid & 15;         // n group: 8 columns each
    const int ty = tid >> 4;         // m group: 4 rows each
    const int m0 = blockIdx.y * BM;
    const int n0 = blockIdx.x * BN;

    const int lr = tid >> 2;         // 0..63, tile row
    const int lk = (tid & 3) * 4;    // 0,4,8,12 — k offset within BK

    const float* aPtr  = g_feat + (size_t)(m0 + lr) * C_ + lk;
    const float* bPtr0 = g_lm   + (size_t)(n0 + lr) * C_ + lk;
    const float* bPtr1 = g_lm   + (size_t)(n0 + lr + 64) * C_ + lk;

    unsigned long long acc[4][4];    // [m][n-pair], f32x2 each
    #pragma unroll
    for (int i = 0; i < 4; i++)
        #pragma unroll
        for (int p = 0; p < 4; p++) acc[i][p] = 0ull;

    float4 aReg  = *(const float4*)aPtr;
    float4 bReg0 = *(const float4*)bPtr0;
    float4 bReg1 = *(const float4*)bPtr1;

    const int NT = C_ / BK;          // 32
    for (int t = 0; t < NT; t++) {
        // commit staged tile to smem
        *(float4*)&As[lr][lk] = aReg;
        Bs[lk + 0][lr] = bReg0.x; Bs[lk + 1][lr] = bReg0.y;
        Bs[lk + 2][lr] = bReg0.z; Bs[lk + 3][lr] = bReg0.w;
        Bs[lk + 0][lr + 64] = bReg1.x; Bs[lk + 1][lr + 64] = bReg1.y;
        Bs[lk + 2][lr + 64] = bReg1.z; Bs[lk + 3][lr + 64] = bReg1.w;
        __syncthreads();

        if (t + 1 < NT) {            // prefetch next tile into registers
            aReg  = *(const float4*)(aPtr  + (t + 1) * BK);
            bReg0 = *(const float4*)(bPtr0 + (t + 1) * BK);
            bReg1 = *(const float4*)(bPtr1 + (t + 1) * BK);
        }

        #pragma unroll
        for (int kk = 0; kk < BK; kk++) {
            float a0 = As[ty * 4 + 0][kk];
            float a1 = As[ty * 4 + 1][kk];
            float a2 = As[ty * 4 + 2][kk];
            float a3 = As[ty * 4 + 3][kk];
            float4 b0 = *(float4*)&Bs[kk][tx * 8];
            float4 b1 = *(float4*)&Bs[kk][tx * 8 + 4];

            unsigned long long bp0 = pack2(b0.x, b0.y);
            unsigned long long bp1 = pack2(b0.z, b0.w);
            unsigned long long bp2 = pack2(b1.x, b1.y);
            unsigned long long bp3 = pack2(b1.z, b1.w);
            unsigned long long ap0 = pack2(a0, a0);
            unsigned long long ap1 = pack2(a1, a1);
            unsigned long long ap2 = pack2(a2, a2);
            unsigned long long ap3 = pack2(a3, a3);

            fma2(acc[0][0], ap0, bp0); fma2(acc[0][1], ap0, bp1);
            fma2(acc[0][2], ap0, bp2); fma2(acc[0][3], ap0, bp3);
            fma2(acc[1][0], ap1, bp0); fma2(acc[1][1], ap1, bp1);
            fma2(acc[1][2], ap1, bp2); fma2(acc[1][3], ap1, bp3);
            fma2(acc[2][0], ap2, bp0); fma2(acc[2][1], ap2, bp1);
            fma2(acc[2][2], ap2, bp2); fma2(acc[2][3], ap2, bp3);
            fma2(acc[3][0], ap3, bp0); fma2(acc[3][1], ap3, bp1);
            fma2(acc[3][2], ap3, bp2); fma2(acc[3][3], ap3, bp3);
        }
        __syncthreads();
    }

    // ---------------- fused epilogue ----------------
    #pragma unroll
    for (int i = 0; i < 4; i++) {
        int mi = m0 + ty * 4 + i;
        float4 q = *(const float4*)(pred_boxes + (size_t)mi * 4);  // cx,cy,w,h
        float qx0 = q.x - 0.5f * q.z, qy0 = q.y - 0.5f * q.w;
        float qx1 = q.x + 0.5f * q.z, qy1 = q.y + 0.5f * q.w;
        float qarea = (qx1 - qx0) * (qy1 - qy0);

        float res[8];
        #pragma unroll
        for (int j = 0; j < 8; j++) {
            int nj = n0 + tx * 8 + j;
            float4 tc = *(const float4*)(g_tbox + nj * 8);      // cx,cy,w,h
            float4 tk = *(const float4*)(g_tbox + nj * 8 + 4);  // x0,y0,x1,y1

            // L1 bbox cost on center-format boxes
            float l1 = fabsf(q.x - tc.x) + fabsf(q.y - tc.y) +
                       fabsf(q.z - tc.z) + fabsf(q.w - tc.w);

            // GIoU on corner boxes
            float tarea = (tk.z - tk.x) * (tk.w - tk.y);
            float ltx = fmaxf(qx0, tk.x), lty = fmaxf(qy0, tk.y);
            float rbx = fminf(qx1, tk.z), rby = fminf(qy1, tk.w);
            float iw = fmaxf(rbx - ltx, 0.f), ih = fmaxf(rby - lty, 0.f);
            float inter = iw * ih;
            float uni = qarea + tarea - inter;
            float iou = inter / uni;
            float ex0 = fminf(qx0, tk.x), ey0 = fminf(qy0, tk.y);
            float ex1 = fmaxf(qx1, tk.z), ey1 = fmaxf(qy1, tk.w);
            float ew = fmaxf(ex1 - ex0, 0.f), eh = fmaxf(ey1 - ey0, 0.f);
            float areaE = ew * eh;
            float giou = iou - (areaE - uni) / areaE;

            float2 cl = unpack2(acc[i][j >> 1]);
            float cls = (j & 1) ? cl.y : cl.x;

            res[j] = 5.0f * l1 + 2.0f * cls - 2.0f * giou;
        }
        size_t off = (size_t)mi * BT_ + n0 + tx * 8;
        *(float4*)(out + off)     = make_float4(res[0], res[1], res[2], res[3]);
        *(float4*)(out + off + 4) = make_float4(res[4], res[5], res[6], res[7]);
    }
}

// ---------------- launcher ----------------
extern "C" void kernel_launch(void* const* d_in, const int* in_sizes, int n_in,
                              void* d_out, int out_size) {
    const float* logits       = (const float*)d_in[0];  // [16,900,512]
    const float* pred_boxes   = (const float*)d_in[1];  // [16,900,4]
    const float* label_maps   = (const float*)d_in[2];  // [16,91,512]
    const float* boxes        = (const float*)d_in[3];  // [16,40,4]
    const int*   class_labels = (const int*)d_in[4];    // [16,40]
    float* out = (float*)d_out;                         // [14400, 640]

    prep_targets_kernel<<<BT_, 128>>>(label_maps, boxes, class_labels);
    prep_feat_kernel<<<(BQ_ * C_ / 4) / 256, 256>>>(logits);
    cost_kernel<<<dim3(BT_ / BN, BQ_ / BM), 256>>>(pred_boxes, out);
}

// round 3
// speedup vs baseline: 3.4944x; 3.4944x over previous
#include <cuda_runtime.h>
#include <cuda_bf16.h>
#include <math.h>
#include <stdint.h>

// ---------------- problem constants ----------------
#define Tt   40
#define Ll   91
#define Cc   512
#define BQn  14400
#define BTn  640
#define MPAD 14464            // 113 * 128
#define KE   1536             // 3 * C (split-bf16 expanded K)

// ---------------- GEMM tiling ----------------
#define BM 128
#define BN 128
#define BK 32                 // bf16 per chunk (64 bytes per row)
#define NCH 48                // KE / BK
#define STAGES 4
#define STAGE_BYTES 16384     // A 8KB + B 8KB
#define DYNSMEM (STAGES * STAGE_BYTES)

// ---------------- scratch (zero-initialized device globals) ----------------
__device__ __nv_bfloat16 g_A[(size_t)MPAD * KE];   // expanded feat (pad rows stay zero)
__device__ __nv_bfloat16 g_B[(size_t)BTn * KE];    // expanded lm
__device__ float         g_tbox[BTn * 8];          // cx,cy,w,h,x0,y0,x1,y1

// ---------------- helpers ----------------
__device__ __forceinline__ uint32_t cvta_s(const void* p) {
    uint32_t a;
    asm("{ .reg .u64 t; cvta.to.shared.u64 t, %1; cvt.u32.u64 %0, t; }"
        : "=r"(a) : "l"(p));
    return a;
}

#define CP16(dst, src) asm volatile("cp.async.cg.shared.global [%0], [%1], 16;" :: "r"(dst), "l"(src))
#define CPCOMMIT()     asm volatile("cp.async.commit_group;")
#define CPWAIT(n)      asm volatile("cp.async.wait_group %0;" :: "n"(n))

__device__ __forceinline__ void ldsm4(uint32_t& r0, uint32_t& r1, uint32_t& r2,
                                      uint32_t& r3, uint32_t addr) {
    asm volatile("ldmatrix.sync.aligned.m8n8.x4.shared.b16 {%0,%1,%2,%3}, [%4];"
                 : "=r"(r0), "=r"(r1), "=r"(r2), "=r"(r3) : "r"(addr));
}

__device__ __forceinline__ void mma_bf16(float* d, const uint32_t* a,
                                         const uint32_t* b) {
    asm volatile(
        "mma.sync.aligned.m16n8k16.row.col.f32.bf16.bf16.f32 "
        "{%0,%1,%2,%3}, {%4,%5,%6,%7}, {%8,%9}, {%0,%1,%2,%3};"
        : "+f"(d[0]), "+f"(d[1]), "+f"(d[2]), "+f"(d[3])
        : "r"(a[0]), "r"(a[1]), "r"(a[2]), "r"(a[3]), "r"(b[0]), "r"(b[1]));
}

// swizzled byte offset for row r (64B rows), 16B-chunk c
__device__ __forceinline__ uint32_t swoff(int r, int c) {
    return (uint32_t)(r * 64 + (((c + (r >> 1)) & 3) << 4));
}

// ---------------- kernel 1: expanded A (focal features, hi/lo split) ----------------
__device__ __forceinline__ float focal_feat(float x) {
    float p = 1.f / (1.f + expf(-x));
    float q = 1.f - p;
    float neg = 0.75f * p * p * (-logf(q + 1e-8f));
    float pos = 0.25f * q * q * (-logf(p + 1e-8f));
    return pos - neg;
}

__global__ void prep_feat(const float* __restrict__ logits) {
    int idx = blockIdx.x * 256 + threadIdx.x;     // one thread = 8 channels
    int base = idx * 8;
    int row = base >> 9;
    int k0 = base & 511;
    float4 x0 = *(const float4*)(logits + base);
    float4 x1 = *(const float4*)(logits + base + 4);
    float f[8] = { x0.x, x0.y, x0.z, x0.w, x1.x, x1.y, x1.z, x1.w };
    __align__(16) __nv_bfloat16 ov[24];
    #pragma unroll
    for (int i = 0; i < 8; i++) {
        float v = focal_feat(f[i]);
        __nv_bfloat16 hi = __float2bfloat16(v);
        __nv_bfloat16 lo = __float2bfloat16(v - __bfloat162float(hi));
        ov[3 * i + 0] = hi; ov[3 * i + 1] = hi; ov[3 * i + 2] = lo;   // (hi, hi, lo)
    }
    uint4* dst = (uint4*)(g_A + (size_t)row * KE + 3 * k0);
    const uint4* s = (const uint4*)ov;
    dst[0] = s[0]; dst[1] = s[1]; dst[2] = s[2];
}

// ---------------- kernel 2: expanded B + target boxes ----------------
__global__ void prep_targets(const float* __restrict__ label_maps,
                             const float* __restrict__ boxes,
                             const int*   __restrict__ class_labels) {
    int j = blockIdx.x;                 // 0..639
    int b = j / Tt;
    int cls = class_labels[j];
    const float* row = label_maps + ((size_t)b * Ll + cls) * Cc;
    int tid = threadIdx.x;              // 256
    float2 v = *(const float2*)(row + tid * 2);
    float s = v.x + v.y;
    #pragma unroll
    for (int o = 16; o; o >>= 1) s += __shfl_xor_sync(0xffffffffu, s, o);
    __shared__ float red[8];
    if ((tid & 31) == 0) red[tid >> 5] = s;
    __syncthreads();
    float tot = red[0] + red[1] + red[2] + red[3] + red[4] + red[5] + red[6] + red[7];
    float inv = 1.f / tot;
    #pragma unroll
    for (int u = 0; u < 2; u++) {
        int c = tid * 2 + u;
        float f = ((u == 0) ? v.x : v.y) * inv;
        __nv_bfloat16 hi = __float2bfloat16(f);
        __nv_bfloat16 lo = __float2bfloat16(f - __bfloat162float(hi));
        size_t o = (size_t)j * KE + 3 * c;
        g_B[o] = hi; g_B[o + 1] = lo; g_B[o + 2] = hi;                // (hi, lo, hi)
    }
    if (tid == 0) {
        float cx = boxes[j * 4 + 0], cy = boxes[j * 4 + 1];
        float w  = boxes[j * 4 + 2], h  = boxes[j * 4 + 3];
        float* o = g_tbox + j * 8;
        o[0] = cx; o[1] = cy; o[2] = w; o[3] = h;
        o[4] = cx - 0.5f * w; o[5] = cy - 0.5f * h;
        o[6] = cx + 0.5f * w; o[7] = cy + 0.5f * h;
    }
}

// ---------------- kernel 3: mma.sync GEMM + fused cost epilogue ----------------
extern __shared__ char dynsmem[];

__global__ __launch_bounds__(256) void cost_kernel(
    const float* __restrict__ pred_boxes,
    float* __restrict__ outp) {

    const int tid = threadIdx.x;
    const int wid = tid >> 5;
    const int lane = tid & 31;
    const int wm = wid & 1;          // 2 warps in M
    const int wn = wid >> 1;         // 4 warps in N
    const int m0 = blockIdx.y * BM;
    const int n0 = blockIdx.x * BN;

    uint32_t smem = cvta_s(dynsmem);

    // per-thread ldmatrix in-stage offsets
    uint32_t aoff[4][2], boff[2][2];
    {
        int ar = wm * 64 + (lane & 15);
        int ac = lane >> 4;
        #pragma unroll
        for (int mt = 0; mt < 4; mt++)
            #pragma unroll
            for (int ks = 0; ks < 2; ks++)
                aoff[mt][ks] = swoff(ar + mt * 16, ks * 2 + ac);
        int br = wn * 32 + ((lane >> 4) << 3) + (lane & 7);
        int bc = (lane >> 3) & 1;
        #pragma unroll
        for (int bp = 0; bp < 2; bp++)
            #pragma unroll
            for (int ks = 0; ks < 2; ks++)
                boff[bp][ks] = 8192u + swoff(br + bp * 16, ks * 2 + bc);
    }

    // cp.async chunk loader (A: 128x32, B: 128x32, 16B granules, swizzled)
    auto issue = [&](int ch) {
        uint32_t st = smem + (ch & (STAGES - 1)) * STAGE_BYTES;
        const __nv_bfloat16* Ag = g_A + (size_t)m0 * KE + ch * BK;
        const __nv_bfloat16* Bg = g_B + (size_t)n0 * KE + ch * BK;
        #pragma unroll
        for (int i = 0; i < 2; i++) {
            int idx = tid + i * 256;
            int r = idx >> 2, c = idx & 3;
            CP16(st + swoff(r, c), Ag + (size_t)r * KE + c * 8);
        }
        #pragma unroll
        for (int i = 0; i < 2; i++) {
            int idx = tid + i * 256;
            int r = idx >> 2, c = idx & 3;
            CP16(st + 8192 + swoff(r, c), Bg + (size_t)r * KE + c * 8);
        }
        CPCOMMIT();
    };

    float acc[4][4][4];
    #pragma unroll
    for (int i = 0; i < 4; i++)
        #pragma unroll
        for (int j = 0; j < 4; j++)
            #pragma unroll
            for (int e = 0; e < 4; e++) acc[i][j][e] = 0.f;

    issue(0); issue(1); issue(2);

    for (int ch = 0; ch < NCH; ch++) {
        if (ch < NCH - 2)      CPWAIT(2);
        else if (ch == NCH - 2) CPWAIT(1);
        else                    CPWAIT(0);
        __syncthreads();
        if (ch + 3 < NCH) issue(ch + 3);

        uint32_t st = smem + (ch & (STAGES - 1)) * STAGE_BYTES;
        #pragma unroll
        for (int ks = 0; ks < 2; ks++) {
            uint32_t a[4][4], b[4][2];
            #pragma unroll
            for (int mt = 0; mt < 4; mt++)
                ldsm4(a[mt][0], a[mt][1], a[mt][2], a[mt][3], st + aoff[mt][ks]);
            #pragma unroll
            for (int bp = 0; bp < 2; bp++)
                ldsm4(b[2 * bp][0], b[2 * bp][1], b[2 * bp + 1][0], b[2 * bp + 1][1],
                      st + boff[bp][ks]);
            #pragma unroll
            for (int mt = 0; mt < 4; mt++)
                #pragma unroll
                for (int nt = 0; nt < 4; nt++)
                    mma_bf16(acc[mt][nt], a[mt], b[nt]);
        }
    }

    // ---------------- fused epilogue (register-resident) ----------------
    const int rbase = m0 + wm * 64 + (lane >> 2);
    const int cbase = n0 + wn * 32 + ((lane & 3) << 1);

    #pragma unroll
    for (int nt = 0; nt < 4; nt++) {
        int n = cbase + nt * 8;
        float4 tc0 = *(const float4*)(g_tbox + n * 8);
        float4 tk0 = *(const float4*)(g_tbox + n * 8 + 4);
        float4 tc1 = *(const float4*)(g_tbox + (n + 1) * 8);
        float4 tk1 = *(const float4*)(g_tbox + (n + 1) * 8 + 4);
        float ta0 = (tk0.z - tk0.x) * (tk0.w - tk0.y);
        float ta1 = (tk1.z - tk1.x) * (tk1.w - tk1.y);

        #pragma unroll
        for (int mt = 0; mt < 4; mt++) {
            #pragma unroll
            for (int half = 0; half < 2; half++) {
                int m = rbase + mt * 16 + half * 8;
                if (m >= BQn) continue;
                float4 qb = *(const float4*)(pred_boxes + (size_t)m * 4);
                float qx0 = qb.x - 0.5f * qb.z, qy0 = qb.y - 0.5f * qb.w;
                float qx1 = qb.x + 0.5f * qb.z, qy1 = qb.y + 0.5f * qb.w;
                float qarea = qb.z * qb.w;

                float r2[2];
                #pragma unroll
                for (int u = 0; u < 2; u++) {
                    float4 tc = u ? tc1 : tc0;
                    float4 tk = u ? tk1 : tk0;
                    float tarea = u ? ta1 : ta0;
                    float l1 = fabsf(qb.x - tc.x) + fabsf(qb.y - tc.y) +
                               fabsf(qb.z - tc.z) + fabsf(qb.w - tc.w);
                    float ltx = fmaxf(qx0, tk.x), lty = fmaxf(qy0, tk.y);
                    float rbx = fminf(qx1, tk.z), rby = fminf(qy1, tk.w);
                    float iw = fmaxf(rbx - ltx, 0.f), ih = fmaxf(rby - lty, 0.f);
                    float inter = iw * ih;
                    float uni = qarea + tarea - inter;
                    float iou = __fdividef(inter, uni);
                    float ex0 = fminf(qx0, tk.x), ey0 = fminf(qy0, tk.y);
                    float ex1 = fmaxf(qx1, tk.z), ey1 = fmaxf(qy1, tk.w);
                    float areaE = fmaxf(ex1 - ex0, 0.f) * fmaxf(ey1 - ey0, 0.f);
                    float giou = iou - __fdividef(areaE - uni, areaE);
                    float cls = acc[mt][nt][half * 2 + u];
                    r2[u] = 5.0f * l1 + 2.0f * cls - 2.0f * giou;
                }
                *(float2*)(outp + (size_t)m * BTn + n) = make_float2(r2[0], r2[1]);
            }
        }
    }
}

// ---------------- launcher ----------------
extern "C" void kernel_launch(void* const* d_in, const int* in_sizes, int n_in,
                              void* d_out, int out_size) {
    const float* logits       = (const float*)d_in[0];
    const float* pred_boxes   = (const float*)d_in[1];
    const float* label_maps   = (const float*)d_in[2];
    const float* boxes        = (const float*)d_in[3];
    const int*   class_labels = (const int*)d_in[4];
    float* out = (float*)d_out;

    cudaFuncSetAttribute(cost_kernel, cudaFuncAttributeMaxDynamicSharedMemorySize, DYNSMEM);

    prep_targets<<<BTn, 256>>>(label_maps, boxes, class_labels);
    prep_feat<<<(BQn * Cc / 8) / 256, 256>>>(logits);
    cost_kernel<<<dim3(BTn / BN, MPAD / BM), 256, DYNSMEM>>>(pred_boxes, out);
}

// round 4
// speedup vs baseline: 6.7758x; 1.9391x over previous
#include <cuda_runtime.h>
#include <cuda_bf16.h>
#include <math.h>
#include <stdint.h>

// ---------------- problem constants ----------------
#define Tt   40
#define Ll   91
#define Cc   512
#define BQn  14400
#define BTn  640
#define MPAD 14464            // 113 * 128

// ---------------- GEMM tiling ----------------
#define BM 128
#define BN 128
#define BK 64                 // bf16 per chunk (128 bytes per row)
#define NCH 8                 // Cc / BK
#define STAGES 3
#define A_BYTES 16384         // 128 x 128B
#define STAGE_BYTES 32768     // A 16KB + B 16KB
#define DYNSMEM (STAGES * STAGE_BYTES)

#define FEAT_BLOCKS 3600      // BQn*Cc/8/256

// ---------------- scratch (zero-initialized device globals) ----------------
__device__ __nv_bfloat16 g_A[(size_t)MPAD * Cc];   // focal features (pad rows stay zero)
__device__ __nv_bfloat16 g_B[(size_t)BTn * Cc];    // normalized label-map rows
__device__ float         g_tbox[BTn * 8];          // cx,cy,w,h,x0,y0,x1,y1

// ---------------- helpers ----------------
__device__ __forceinline__ uint32_t cvta_s(const void* p) {
    uint32_t a;
    asm("{ .reg .u64 t; cvta.to.shared.u64 t, %1; cvt.u32.u64 %0, t; }"
        : "=r"(a) : "l"(p));
    return a;
}

#define CP16(dst, src) asm volatile("cp.async.cg.shared.global [%0], [%1], 16;" :: "r"(dst), "l"(src))
#define CPCOMMIT()     asm volatile("cp.async.commit_group;")
#define CPWAIT(n)      asm volatile("cp.async.wait_group %0;" :: "n"(n))

__device__ __forceinline__ void ldsm4(uint32_t& r0, uint32_t& r1, uint32_t& r2,
                                      uint32_t& r3, uint32_t addr) {
    asm volatile("ldmatrix.sync.aligned.m8n8.x4.shared.b16 {%0,%1,%2,%3}, [%4];"
                 : "=r"(r0), "=r"(r1), "=r"(r2), "=r"(r3) : "r"(addr));
}

__device__ __forceinline__ void mma_bf16(float* d, const uint32_t* a,
                                         const uint32_t* b) {
    asm volatile(
        "mma.sync.aligned.m16n8k16.row.col.f32.bf16.bf16.f32 "
        "{%0,%1,%2,%3}, {%4,%5,%6,%7}, {%8,%9}, {%0,%1,%2,%3};"
        : "+f"(d[0]), "+f"(d[1]), "+f"(d[2]), "+f"(d[3])
        : "r"(a[0]), "r"(a[1]), "r"(a[2]), "r"(a[3]), "r"(b[0]), "r"(b[1]));
}

// swizzled byte offset: 128B rows, 8 chunks of 16B, 8-way XOR
__device__ __forceinline__ uint32_t swoff(int r, int c) {
    return (uint32_t)(r * 128 + ((c ^ (r & 7)) << 4));
}

// ---------------- focal feature ----------------
__device__ __forceinline__ float focal_feat(float x) {
    float p = 1.f / (1.f + expf(-x));
    float q = 1.f - p;
    float neg = 0.75f * p * p * (-logf(q + 1e-8f));
    float pos = 0.25f * q * q * (-logf(p + 1e-8f));
    return pos - neg;
}

// ---------------- kernel 1: fused prep (features + targets) ----------------
__global__ void prep_kernel(const float* __restrict__ logits,
                            const float* __restrict__ label_maps,
                            const float* __restrict__ boxes,
                            const int*   __restrict__ class_labels) {
    int bid = blockIdx.x;
    int tid = threadIdx.x;
    if (bid < FEAT_BLOCKS) {
        // ---- focal features: one thread = 8 channels ----
        int base = (bid * 256 + tid) * 8;
        float4 x0 = *(const float4*)(logits + base);
        float4 x1 = *(const float4*)(logits + base + 4);
        float f[8] = { x0.x, x0.y, x0.z, x0.w, x1.x, x1.y, x1.z, x1.w };
        __align__(16) __nv_bfloat16 ov[8];
        #pragma unroll
        for (int i = 0; i < 8; i++) ov[i] = __float2bfloat16(focal_feat(f[i]));
        *(uint4*)(g_A + base) = *(const uint4*)ov;
    } else {
        // ---- targets: one block per target row ----
        int j = bid - FEAT_BLOCKS;          // 0..639
        int b = j / Tt;
        int cls = class_labels[j];
        const float* row = label_maps + ((size_t)b * Ll + cls) * Cc;
        float2 v = *(const float2*)(row + tid * 2);
        float s = v.x + v.y;
        #pragma unroll
        for (int o = 16; o; o >>= 1) s += __shfl_xor_sync(0xffffffffu, s, o);
        __shared__ float red[8];
        if ((tid & 31) == 0) red[tid >> 5] = s;
        __syncthreads();
        float inv = 1.f / (red[0] + red[1] + red[2] + red[3] +
                           red[4] + red[5] + red[6] + red[7]);
        __nv_bfloat16 h0 = __float2bfloat16(v.x * inv);
        __nv_bfloat16 h1 = __float2bfloat16(v.y * inv);
        *(__nv_bfloat162*)(g_B + (size_t)j * Cc + tid * 2) =
            __nv_bfloat162(h0, h1);
        if (tid == 0) {
            float cx = boxes[j * 4 + 0], cy = boxes[j * 4 + 1];
            float w  = boxes[j * 4 + 2], h  = boxes[j * 4 + 3];
            float* o = g_tbox + j * 8;
            o[0] = cx; o[1] = cy; o[2] = w; o[3] = h;
            o[4] = cx - 0.5f * w; o[5] = cy - 0.5f * h;
            o[6] = cx + 0.5f * w; o[7] = cy + 0.5f * h;
        }
    }
}

// ---------------- kernel 2: mma.sync GEMM + fused cost epilogue ----------------
extern __shared__ char dynsmem[];

__global__ __launch_bounds__(256, 2) void cost_kernel(
    const float* __restrict__ pred_boxes,
    float* __restrict__ outp) {

    const int tid = threadIdx.x;
    const int wid = tid >> 5;
    const int lane = tid & 31;
    const int wm = wid & 1;          // 2 warps in M
    const int wn = wid >> 1;         // 4 warps in N
    const int m0 = blockIdx.y * BM;
    const int n0 = blockIdx.x * BN;

    uint32_t smem = cvta_s(dynsmem);

    // per-thread ldmatrix in-stage offsets (4 k16-steps per BK=64 chunk)
    uint32_t aoff[4][4], boff[2][4];
    {
        int ar = wm * 64 + (lane & 15);
        int ac = lane >> 4;                       // 0..1
        #pragma unroll
        for (int mt = 0; mt < 4; mt++)
            #pragma unroll
            for (int ks = 0; ks < 4; ks++)
                aoff[mt][ks] = swoff(ar + mt * 16, ks * 2 + ac);
        int br = wn * 32 + ((lane >> 4) << 3) + (lane & 7);
        int bc = (lane >> 3) & 1;
        #pragma unroll
        for (int bp = 0; bp < 2; bp++)
            #pragma unroll
            for (int ks = 0; ks < 4; ks++)
                boff[bp][ks] = (uint32_t)A_BYTES + swoff(br + bp * 16, ks * 2 + bc);
    }

    // cp.async chunk loader: A 128x64 bf16, B 128x64 bf16, swizzled 16B granules
    auto issue = [&](int ch) {
        uint32_t st = smem + (ch % STAGES) * STAGE_BYTES;
        const __nv_bfloat16* Ag = g_A + (size_t)m0 * Cc + ch * BK;
        const __nv_bfloat16* Bg = g_B + (size_t)n0 * Cc + ch * BK;
        #pragma unroll
        for (int i = 0; i < 4; i++) {
            int idx = tid + i * 256;              // 0..1023
            int r = idx >> 3, c = idx & 7;
            CP16(st + swoff(r, c), Ag + (size_t)r * Cc + c * 8);
        }
        #pragma unroll
        for (int i = 0; i < 4; i++) {
            int idx = tid + i * 256;
            int r = idx >> 3, c = idx & 7;
            CP16(st + A_BYTES + swoff(r, c), Bg + (size_t)r * Cc + c * 8);
        }
        CPCOMMIT();
    };

    float acc[4][4][4];
    #pragma unroll
    for (int i = 0; i < 4; i++)
        #pragma unroll
        for (int j = 0; j < 4; j++)
            #pragma unroll
            for (int e = 0; e < 4; e++) acc[i][j][e] = 0.f;

    issue(0); issue(1);

    for (int ch = 0; ch < NCH; ch++) {
        if (ch < NCH - 1) CPWAIT(1); else CPWAIT(0);
        __syncthreads();
        if (ch + 2 < NCH) issue(ch + 2);

        uint32_t st = smem + (ch % STAGES) * STAGE_BYTES;
        #pragma unroll
        for (int ks = 0; ks < 4; ks++) {
            uint32_t a[4][4], b[4][2];
            #pragma unroll
            for (int mt = 0; mt < 4; mt++)
                ldsm4(a[mt][0], a[mt][1], a[mt][2], a[mt][3], st + aoff[mt][ks]);
            #pragma unroll
            for (int bp = 0; bp < 2; bp++)
                ldsm4(b[2 * bp][0], b[2 * bp][1], b[2 * bp + 1][0], b[2 * bp + 1][1],
                      st + boff[bp][ks]);
            #pragma unroll
            for (int mt = 0; mt < 4; mt++)
                #pragma unroll
                for (int nt = 0; nt < 4; nt++)
                    mma_bf16(acc[mt][nt], a[mt], b[nt]);
        }
    }

    // ---------------- fused epilogue (register-resident) ----------------
    const int rbase = m0 + wm * 64 + (lane >> 2);
    const int cbase = n0 + wn * 32 + ((lane & 3) << 1);

    #pragma unroll
    for (int nt = 0; nt < 4; nt++) {
        int n = cbase + nt * 8;
        float4 tc0 = *(const float4*)(g_tbox + n * 8);
        float4 tk0 = *(const float4*)(g_tbox + n * 8 + 4);
        float4 tc1 = *(const float4*)(g_tbox + (n + 1) * 8);
        float4 tk1 = *(const float4*)(g_tbox + (n + 1) * 8 + 4);
        float ta0 = (tk0.z - tk0.x) * (tk0.w - tk0.y);
        float ta1 = (tk1.z - tk1.x) * (tk1.w - tk1.y);

        #pragma unroll
        for (int mt = 0; mt < 4; mt++) {
            #pragma unroll
            for (int half = 0; half < 2; half++) {
                int m = rbase + mt * 16 + half * 8;
                if (m >= BQn) continue;
                float4 qb = *(const float4*)(pred_boxes + (size_t)m * 4);
                float qx0 = qb.x - 0.5f * qb.z, qy0 = qb.y - 0.5f * qb.w;
                float qx1 = qb.x + 0.5f * qb.z, qy1 = qb.y + 0.5f * qb.w;
                float qarea = qb.z * qb.w;

                float r2[2];
                #pragma unroll
                for (int u = 0; u < 2; u++) {
                    float4 tc = u ? tc1 : tc0;
                    float4 tk = u ? tk1 : tk0;
                    float tarea = u ? ta1 : ta0;
                    float l1 = fabsf(qb.x - tc.x) + fabsf(qb.y - tc.y) +
                               fabsf(qb.z - tc.z) + fabsf(qb.w - tc.w);
                    float ltx = fmaxf(qx0, tk.x), lty = fmaxf(qy0, tk.y);
                    float rbx = fminf(qx1, tk.z), rby = fminf(qy1, tk.w);
                    float iw = fmaxf(rbx - ltx, 0.f), ih = fmaxf(rby - lty, 0.f);
                    float inter = iw * ih;
                    float uni = qarea + tarea - inter;
                    float iou = __fdividef(inter, uni);
                    float ex0 = fminf(qx0, tk.x), ey0 = fminf(qy0, tk.y);
                    float ex1 = fmaxf(qx1, tk.z), ey1 = fmaxf(qy1, tk.w);
                    float areaE = fmaxf(ex1 - ex0, 0.f) * fmaxf(ey1 - ey0, 0.f);
                    float giou = iou - __fdividef(areaE - uni, areaE);
                    float cls = acc[mt][nt][half * 2 + u];
                    r2[u] = 5.0f * l1 + 2.0f * cls - 2.0f * giou;
                }
                *(float2*)(outp + (size_t)m * BTn + n) = make_float2(r2[0], r2[1]);
            }
        }
    }
}

// ---------------- launcher ----------------
extern "C" void kernel_launch(void* const* d_in, const int* in_sizes, int n_in,
                              void* d_out, int out_size) {
    const float* logits       = (const float*)d_in[0];
    const float* pred_boxes   = (const float*)d_in[1];
    const float* label_maps   = (const float*)d_in[2];
    const float* boxes        = (const float*)d_in[3];
    const int*   class_labels = (const int*)d_in[4];
    float* out = (float*)d_out;

    cudaFuncSetAttribute(cost_kernel, cudaFuncAttributeMaxDynamicSharedMemorySize, DYNSMEM);

    prep_kernel<<<FEAT_BLOCKS + BTn, 256>>>(logits, label_maps, boxes, class_labels);
    cost_kernel<<<dim3(BTn / BN, MPAD / BM), 256, DYNSMEM>>>(pred_boxes, out);
}